// round 16
// baseline (speedup 1.0000x reference)
#include <cuda_runtime.h>

// QuantumRecurrentUnit — closed-form reduction, 2 lanes per chain, scalar
// polynomial sincos (trimmed) + store-in-shuffle-shadow scheduling.
//
// Per step: theta_q = prev_q + x_q;  P_m = prod_{q<=m} cos theta_q;
//   out_m = cos(w_m)*P_m - sin(w_m)*sin(theta_m)*sin(theta_{m+1})  (m<5)
//   out_5 = cos(w_5)*P_5 - sin(w_5)*sin(theta_5)
//
// R14: R13 (f32x2) regressed — pack/unpack movs lengthened the serial chain
// and nothing hides latency at 1 warp/SMSP. Revert to R12 scalar; cut FFMA
// count (1-term CW, 4-term cephes sin/cos, fold cross-lane mul into weight)
// and store the PREVIOUS step's outputs inside the 26-cyc SHFL shadow.

#define NQ 6
#define T_STEPS 1024
#define C_IN 16
#define PF 8   // prefetch ring depth in steps (divides T_STEPS)

#define INVPIf ( 0.3183098861837907f)
#define MAGICf ( 12582912.0f)        // 1.5 * 2^23
#define PIF    ( 3.14159274101257f)  // float-rounded pi (|k|<=3 -> err 2.6e-7)

__device__ __forceinline__ float fxor(float v, unsigned s) {
    return __uint_as_float(__float_as_uint(v) ^ s);
}

// sincos(th) for |th| <~ 16: magic-number rint(th/pi), 1-term CW, cephes
// 4-term polynomials on [-pi/2, pi/2], shared (-1)^k sign via XOR.
// ~13 fma-pipe ops + ~3 alu ops.
__device__ __forceinline__ void psincos(float th, float& s, float& c) {
    float fk = fmaf(th, INVPIf, MAGICf);
    unsigned sgn = __float_as_uint(fk) << 31;   // parity of k as sign bit
    float k = fk - MAGICf;
    float r = fmaf(k, -PIF, th);                // r in [-pi/2, pi/2]
    float r2 = r * r;
    float ts = fmaf(2.7183114939e-6f, r2, -1.9840782426e-4f);
    ts = fmaf(ts, r2, 8.3333213500e-3f);
    ts = fmaf(ts, r2, -1.6666666664e-1f);
    float sv = fmaf(ts * r2, r, r);
    float tc = fmaf(2.4433157484e-5f, r2, -1.3887316255e-3f);
    tc = fmaf(tc, r2, 4.1666645683e-2f);
    tc = fmaf(tc, r2, -0.5f);
    float cv = fmaf(tc, r2, 1.0f);
    s = fxor(sv, sgn);
    c = fxor(cv, sgn);
}

__global__ void __launch_bounds__(32, 1)
qru_kernel(const float* __restrict__ x, const float* __restrict__ w,
           float* __restrict__ out, int B) {
    int gt   = blockIdx.x * 32 + threadIdx.x;
    int pair = gt >> 1;          // chain index
    int r    = gt & 1;           // 0: wires 0-2, 1: wires 3-5
    if (pair >= B) return;
    // Both lanes of a pair are jointly active/inactive -> pair-local bfly
    // under the active mask is convergence-safe.
    unsigned mask = __activemask();

    // This lane's 3 weights (once).
    float cwA, swA, cwB, swB, cwC, swC;
    psincos(__ldg(w + r * 3 + 0), swA, cwA);
    psincos(__ldg(w + r * 3 + 1), swB, cwB);
    psincos(__ldg(w + r * 3 + 2), swC, cwC);
    float nswA = -swA, nswB = -swB, nswC = -swC;

    const float*  xb  = x + (size_t)pair * (T_STEPS * C_IN);
    const float4* xp4 = reinterpret_cast<const float4*>(xb);   // row t: xp4 + t*4
    const float2* xp2 = reinterpret_cast<const float2*>(xb);   // x4,x5: xp2[t*8+2]
    float* __restrict__ op = out + (size_t)pair * (T_STEPS * NQ);

    float pA = 0.f, pB = 0.f, pC = 0.f;

    // Prefetch ring (both lanes of a pair load same addresses: broadcast).
    float4 rA[PF];
    float2 rB[PF];
    #pragma unroll
    for (int d = 0; d < PF; d++) {
        rA[d] = __ldg(xp4 + d * 4);
        rB[d] = __ldg(xp2 + d * 8 + 2);
    }

    const float onef = 1.0f;

    for (int tb = 0; tb < T_STEPS; tb += PF) {
        bool more = (tb + PF) < T_STEPS;
        #pragma unroll
        for (int u = 0; u < PF; u++) {
            const int t = tb + u;
            // Per-lane inputs: lane0 -> x0,x1,x2 ; lane1 -> x3,x4,x5.
            float xA = r ? rA[u].w : rA[u].x;
            float xB = r ? rB[u].x : rA[u].y;
            float xC = r ? rB[u].y : rA[u].z;

            if (more) {   // refill slot for step t+PF (covers DRAM latency)
                rA[u] = __ldg(xp4 + (t + PF) * 4);
                rB[u] = __ldg(xp2 + (t + PF) * 8 + 2);
            }

            float sA, cA, sB, cB, sC, cC;
            psincos(pA + xA, sA, cA);
            psincos(pB + xB, sB, cB);
            psincos(pC + xC, sC, cC);

            float t1  = cA * cB;
            float t2  = t1 * cC;            // lane0: P2 = c0c1c2
            float send = r ? sA : t2;       // lane1 sends s3, lane0 sends P2
            float recv = __shfl_xor_sync(mask, send, 1);

            // ---- SHFL shadow: store PREVIOUS step's outputs (pA,pB,pC
            // still hold step t-1 results here). 24B per chain total.
            // lane0: {pA,pB} @ elem 0, pC @ elem 2  (byte 24(t-1)   : 8-aligned)
            // lane1: {pB,pC} @ elem 4, pA @ elem 3  (byte 24(t-1)+16: 8-aligned)
            if (t > 0) {
                float* o = op + (t - 1) * NQ;
                float2 v2 = r ? make_float2(pB, pC) : make_float2(pA, pB);
                *reinterpret_cast<float2*>(o + (r ? 4 : 0)) = v2;
                o[r ? 3 : 2] = r ? pA : pC;
            }

            // ---- consume recv: fold cross-lane multiplier into weights.
            float mul  = r ? recv : onef;          // lane1: P2 from lane0
            float cwAr = cwA * mul;
            float cwBr = cwB * mul;
            float cwCr = cwC * mul;

            float sAB = sA * sB;
            float sBC = sB * sC;
            float sCl = sC * (r ? onef : recv);    // lane0: s2*s3, lane1: s5

            pA = fmaf(cwAr, cA, nswA * sAB);
            pB = fmaf(cwBr, t1, nswB * sBC);
            pC = fmaf(cwCr, t2, nswC * sCl);
        }
    }

    // Epilogue: store the final step's outputs.
    {
        float* o = op + (T_STEPS - 1) * NQ;
        float2 v2 = r ? make_float2(pB, pC) : make_float2(pA, pB);
        *reinterpret_cast<float2*>(o + (r ? 4 : 0)) = v2;
        o[r ? 3 : 2] = r ? pA : pC;
    }
}

extern "C" void kernel_launch(void* const* d_in, const int* in_sizes, int n_in,
                              void* d_out, int out_size) {
    // Inputs per metadata order: x (B*1024*16 f32), weight (6 f32).
    const float* x = (const float*)d_in[0];
    const float* w = (const float*)d_in[1];
    if (n_in >= 2 && in_sizes[0] == NQ) {  // defensive: identify by size
        const float* tmp = x; x = w; w = tmp;
    }
    float* out = (float*)d_out;

    int B = out_size / (T_STEPS * NQ);
    int threads = 2 * B;                       // 2 lanes per chain
    int blocks  = (threads + 31) / 32;         // 1 warp per block -> spread over SMs
    qru_kernel<<<blocks, 32>>>(x, w, out, B);
}

// round 17
// speedup vs baseline: 1.2593x; 1.2593x over previous
#include <cuda_runtime.h>

// QuantumRecurrentUnit — closed-form reduction, 2 lanes per chain.
//
// Per step: theta_q = prev_q + x_q;  P_m = prod_{q<=m} cos theta_q;
//   out_m = cos(w_m)*P_m - sin(w_m)*sin(theta_m)*sin(theta_{m+1})  (m<5)
//   out_5 = cos(w_5)*P_5 - sin(w_5)*sin(theta_5)
//
// R17: revert to the exact 121us R12 structure (R14's store-skew regressed;
// schedule-fragile at 1 warp/SMSP). ONLY change vs R12: psincos internals —
//   * 1-term Cody-Waite (validated by R16: rel_err 4.5e-6 vs 1e-3 tol)
//   * 4-term cephes polys in ESTRIN form with constant multipliers and
//     register-held addends -> ptxas can emit FFMA-imm (rt_SMSP=1, 2x tput)
//     for 6 of 13 FFMAs per sincos; also shortens poly chain 16->12.

#define NQ 6
#define T_STEPS 1024
#define C_IN 16
#define PF 16   // prefetch ring depth in steps (divides T_STEPS)

#define INVPIf ( 0.3183098861837907f)
#define MAGICf ( 12582912.0f)        // 1.5 * 2^23
#define PIF    ( 3.14159274101257f)  // float-rounded pi (|k|<=3 -> err 2.6e-7)

#define S4f ( 2.7183114939e-6f)
#define S3f (-1.9840782426e-4f)
#define S2f ( 8.3333213500e-3f)
#define S1f (-1.6666666664e-1f)
#define C4f ( 2.4433157484e-5f)
#define C3f (-1.3887316255e-3f)
#define C2f ( 4.1666645683e-2f)
#define C1f (-0.5f)

__device__ __forceinline__ float fxor(float v, unsigned s) {
    return __uint_as_float(__float_as_uint(v) ^ s);
}

// Estrin sincos: 1-term CW range reduction, cephes-4 polynomials.
// Constant multipliers + register addends -> FFMA-imm (rt 1) eligible.
__device__ __forceinline__ void psincos(float th, float& s, float& c,
                                        float MAGr, float S3a, float S1a,
                                        float C3a, float C1a, float onef) {
    float fk = fmaf(th, INVPIf, MAGr);
    unsigned sg = __float_as_uint(fk) << 31;    // parity of k as sign bit
    float k  = fk - MAGICf;
    float rr = fmaf(k, -PIF, th);               // r in [-pi/2, pi/2]
    float r2 = rr * rr;
    float r4 = r2 * r2;
    float e0 = fmaf(r2, S4f, S3a);              // imm-mul
    float e1 = fmaf(r2, S2f, S1a);              // imm-mul
    float ps = fmaf(e0, r4, e1);
    float sv = fmaf(ps * r2, rr, rr);
    float q0 = fmaf(r2, C4f, C3a);              // imm-mul
    float q1 = fmaf(r2, C2f, C1a);              // imm-mul
    float qc = fmaf(q0, r4, q1);
    float cv = fmaf(qc, r2, onef);
    s = fxor(sv, sg);
    c = fxor(cv, sg);
}

__global__ void __launch_bounds__(32, 1)
qru_kernel(const float* __restrict__ x, const float* __restrict__ w,
           float* __restrict__ out, int B) {
    int gt   = blockIdx.x * 32 + threadIdx.x;
    int pair = gt >> 1;          // chain index
    int r    = gt & 1;           // 0: wires 0-2, 1: wires 3-5
    if (pair >= B) return;
    // Both lanes of a pair are jointly active/inactive -> pair-local bfly
    // under the active mask is convergence-safe.
    unsigned mask = __activemask();

    // Register-held addends (imm-form FFMA needs a register addend).
    float MAGr = MAGICf;
    float S3a = S3f, S1a = S1f, C3a = C3f, C1a = C1f;
    const float onef = 1.0f;

    // This lane's 3 weights (once).
    float cwA, swA, cwB, swB, cwC, swC;
    psincos(__ldg(w + r * 3 + 0), swA, cwA, MAGr, S3a, S1a, C3a, C1a, onef);
    psincos(__ldg(w + r * 3 + 1), swB, cwB, MAGr, S3a, S1a, C3a, C1a, onef);
    psincos(__ldg(w + r * 3 + 2), swC, cwC, MAGr, S3a, S1a, C3a, C1a, onef);

    const float*  xb  = x + (size_t)pair * (T_STEPS * C_IN);
    const float4* xp4 = reinterpret_cast<const float4*>(xb);   // row t: xp4 + t*4
    const float2* xp2 = reinterpret_cast<const float2*>(xb);   // x4,x5: xp2[t*8+2]
    float* __restrict__ op = out + (size_t)pair * (T_STEPS * NQ);

    float pA = 0.f, pB = 0.f, pC = 0.f;

    // Prefetch ring: both lanes of a pair load the same addresses (broadcast).
    float4 rA[PF];
    float2 rB[PF];
    #pragma unroll
    for (int d = 0; d < PF; d++) {
        rA[d] = __ldg(xp4 + d * 4);
        rB[d] = __ldg(xp2 + d * 8 + 2);
    }

    for (int tb = 0; tb < T_STEPS; tb += PF) {
        bool more = (tb + PF) < T_STEPS;
        #pragma unroll
        for (int u = 0; u < PF; u++) {
            const int t = tb + u;
            // Per-lane inputs: lane0 -> x0,x1,x2 ; lane1 -> x3,x4,x5.
            float xA = r ? rA[u].w : rA[u].x;
            float xB = r ? rB[u].x : rA[u].y;
            float xC = r ? rB[u].y : rA[u].z;

            if (more) {   // refill slot for step t+PF (covers DRAM latency)
                rA[u] = __ldg(xp4 + (t + PF) * 4);
                rB[u] = __ldg(xp2 + (t + PF) * 8 + 2);
            }

            float sA, cA, sB, cB, sC, cC;
            psincos(pA + xA, sA, cA, MAGr, S3a, S1a, C3a, C1a, onef);
            psincos(pB + xB, sB, cB, MAGr, S3a, S1a, C3a, C1a, onef);
            psincos(pC + xC, sC, cC, MAGr, S3a, S1a, C3a, C1a, onef);

            float t1  = cA * cB;
            float t2  = t1 * cC;            // lane0: P2 = c0c1c2
            float send = r ? sA : t2;       // lane1 sends s3, lane0 sends P2
            float recv = __shfl_xor_sync(mask, send, 1);

            float mul = r ? recv : onef;    // lane1: P2 from lane0
            float PA  = mul * cA;
            float PB  = mul * t1;
            float PC  = mul * t2;

            float sAB = sA * sB;
            float sBC = sB * sC;
            float sCl = sC * (r ? onef : recv);   // lane0: s2*s3, lane1: s5

            pA = fmaf(cwA, PA, -swA * sAB);
            pB = fmaf(cwB, PB, -swB * sBC);
            pC = fmaf(cwC, PC, -swC * sCl);

            // Store 12B per lane, contiguous across the pair (24B per chain).
            // lane0: {pA,pB} @ elem 0, pC @ elem 2  (byte 24t    : 8-aligned)
            // lane1: {pB,pC} @ elem 4, pA @ elem 3  (byte 24t+16 : 8-aligned)
            float* o = op + t * NQ;
            float2 v2 = r ? make_float2(pB, pC) : make_float2(pA, pB);
            *reinterpret_cast<float2*>(o + (r ? 4 : 0)) = v2;
            o[r ? 3 : 2] = r ? pA : pC;
        }
    }
}

extern "C" void kernel_launch(void* const* d_in, const int* in_sizes, int n_in,
                              void* d_out, int out_size) {
    // Inputs per metadata order: x (B*1024*16 f32), weight (6 f32).
    const float* x = (const float*)d_in[0];
    const float* w = (const float*)d_in[1];
    if (n_in >= 2 && in_sizes[0] == NQ) {  // defensive: identify by size
        const float* tmp = x; x = w; w = tmp;
    }
    float* out = (float*)d_out;

    int B = out_size / (T_STEPS * NQ);
    int threads = 2 * B;                       // 2 lanes per chain
    int blocks  = (threads + 31) / 32;         // 1 warp per block -> spread over SMs
    qru_kernel<<<blocks, 32>>>(x, w, out, B);
}